// round 2
// baseline (speedup 1.0000x reference)
#include <cuda_runtime.h>
#include <cuda_bf16.h>
#include <cstdint>
#include <cstddef>

// Problem constants
#define BB 8
#define TT 2048
#define DD 1024

// GEMM tiling
#define BM 128
#define BN 128
#define BK 32
#define SST 36   // smem row stride (floats): 36%32=4 -> conflict-free fragment loads

// Scratch: transposed W (col-major B operand for GEMM1). Device global = allowed.
__device__ float d_Wt[DD * DD];

__device__ __forceinline__ uint32_t f2tf32(float x) {
    uint32_t r;
    asm("cvt.rna.tf32.f32 %0, %1;" : "=r"(r) : "f"(x));
    return r;
}

__device__ __forceinline__ void mma_tf32(float c[4], const uint32_t a[4], const uint32_t b[2]) {
    asm volatile(
        "mma.sync.aligned.m16n8k8.row.col.f32.tf32.tf32.f32 "
        "{%0,%1,%2,%3}, {%4,%5,%6,%7}, {%8,%9}, {%0,%1,%2,%3};\n"
        : "+f"(c[0]), "+f"(c[1]), "+f"(c[2]), "+f"(c[3])
        : "r"(a[0]), "r"(a[1]), "r"(a[2]), "r"(a[3]), "r"(b[0]), "r"(b[1]));
}

// W [K][N] row-major -> Wt [N][K] row-major (i.e. col-major B)
__global__ void transposeW(const float* __restrict__ W, float* __restrict__ Wt) {
    __shared__ float tile[32][33];
    int bx = blockIdx.x * 32, by = blockIdx.y * 32;
    int tx = threadIdx.x, ty = threadIdx.y;
#pragma unroll
    for (int i = 0; i < 32; i += 8)
        tile[ty + i][tx] = W[(size_t)(by + ty + i) * DD + bx + tx];
    __syncthreads();
#pragma unroll
    for (int i = 0; i < 32; i += 8)
        Wt[(size_t)(bx + ty + i) * DD + by + tx] = tile[tx][ty + i];
}

// C[M,N] = A[M,K] (row-major, ld=lda) @ B[N,K]^T (B stored [n][k], ld=ldb)
// Batched over blockIdx.z via strides. All dims divisible by tiles (no bounds checks).
__global__ __launch_bounds__(256) void gemm_tf32(
    const float* __restrict__ A, const float* __restrict__ Bm, float* __restrict__ C,
    int K, int lda, int ldb, int ldc,
    size_t aStride, size_t bStride, size_t cStride)
{
    __shared__ uint32_t sA[BM * SST];
    __shared__ uint32_t sB[BN * SST];

    A  += (size_t)blockIdx.z * aStride;
    Bm += (size_t)blockIdx.z * bStride;
    C  += (size_t)blockIdx.z * cStride;

    const int tid  = threadIdx.x;
    const int warp = tid >> 5;
    const int lane = tid & 31;
    const int wm = warp & 3;      // 4 warps along M -> 32 rows each
    const int wn = warp >> 2;     // 2 warps along N -> 64 cols each
    const int g = lane >> 2;      // 0..7
    const int t = lane & 3;       // 0..3

    // global->smem load mapping: 256 threads, each 4x float4 per operand
    const int lrow = tid >> 3;        // 0..31 (+i*32)
    const int lk   = (tid & 7) * 4;   // 0..28

    const float* Ag = A  + (size_t)((size_t)blockIdx.y * BM + lrow) * lda + lk;
    const float* Bg = Bm + (size_t)((size_t)blockIdx.x * BN + lrow) * ldb + lk;

    float c[2][8][4];
#pragma unroll
    for (int mt = 0; mt < 2; mt++)
#pragma unroll
        for (int nt = 0; nt < 8; nt++)
#pragma unroll
            for (int i = 0; i < 4; i++) c[mt][nt][i] = 0.f;

    for (int k0 = 0; k0 < K; k0 += BK) {
#pragma unroll
        for (int i = 0; i < 4; i++) {
            float4 av = *(const float4*)(Ag + (size_t)i * 32 * lda + k0);
            float4 bv = *(const float4*)(Bg + (size_t)i * 32 * ldb + k0);
            int r = lrow + i * 32;
            uint32_t* pa = &sA[r * SST + lk];
            pa[0] = f2tf32(av.x); pa[1] = f2tf32(av.y);
            pa[2] = f2tf32(av.z); pa[3] = f2tf32(av.w);
            uint32_t* pb = &sB[r * SST + lk];
            pb[0] = f2tf32(bv.x); pb[1] = f2tf32(bv.y);
            pb[2] = f2tf32(bv.z); pb[3] = f2tf32(bv.w);
        }
        __syncthreads();

#pragma unroll
        for (int ks = 0; ks < 4; ks++) {
            const int kk = ks * 8;
            uint32_t a[2][4], b[8][2];
#pragma unroll
            for (int mt = 0; mt < 2; mt++) {
                int rm = wm * 32 + mt * 16;
                a[mt][0] = sA[(rm + g)     * SST + kk + t];
                a[mt][1] = sA[(rm + g + 8) * SST + kk + t];
                a[mt][2] = sA[(rm + g)     * SST + kk + t + 4];
                a[mt][3] = sA[(rm + g + 8) * SST + kk + t + 4];
            }
#pragma unroll
            for (int nt = 0; nt < 8; nt++) {
                int rn = wn * 64 + nt * 8 + g;
                b[nt][0] = sB[rn * SST + kk + t];
                b[nt][1] = sB[rn * SST + kk + t + 4];
            }
#pragma unroll
            for (int mt = 0; mt < 2; mt++)
#pragma unroll
                for (int nt = 0; nt < 8; nt++)
                    mma_tf32(c[mt][nt], a[mt], b[nt]);
        }
        __syncthreads();
    }

    // epilogue: c0/c1 contiguous along n -> float2 stores
    const int mbase = blockIdx.y * BM + wm * 32;
    const int nbase = blockIdx.x * BN + wn * 64;
#pragma unroll
    for (int mt = 0; mt < 2; mt++) {
        int row0 = mbase + mt * 16 + g;
#pragma unroll
        for (int nt = 0; nt < 8; nt++) {
            int col = nbase + nt * 8 + t * 2;
            float2 v0 = make_float2(c[mt][nt][0], c[mt][nt][1]);
            *(float2*)&C[(size_t)row0 * ldc + col] = v0;
            float2 v1 = make_float2(c[mt][nt][2], c[mt][nt][3]);
            *(float2*)&C[(size_t)(row0 + 8) * ldc + col] = v1;
        }
    }
}

// In-place softmax over rows of length 1024. One block (256 thr) per row.
__global__ __launch_bounds__(256) void softmax_rows(float* __restrict__ data) {
    __shared__ float redmax[8];
    __shared__ float redsum[8];
    float* p = data + (size_t)blockIdx.x * DD;
    const int tid = threadIdx.x;

    float4 v = *(float4*)(p + tid * 4);
    float m = fmaxf(fmaxf(v.x, v.y), fmaxf(v.z, v.w));
#pragma unroll
    for (int o = 16; o > 0; o >>= 1) m = fmaxf(m, __shfl_xor_sync(0xffffffffu, m, o));
    if ((tid & 31) == 0) redmax[tid >> 5] = m;
    __syncthreads();
    m = redmax[0];
#pragma unroll
    for (int i = 1; i < 8; i++) m = fmaxf(m, redmax[i]);

    v.x = __expf(v.x - m); v.y = __expf(v.y - m);
    v.z = __expf(v.z - m); v.w = __expf(v.w - m);
    float s = v.x + v.y + v.z + v.w;
#pragma unroll
    for (int o = 16; o > 0; o >>= 1) s += __shfl_xor_sync(0xffffffffu, s, o);
    if ((tid & 31) == 0) redsum[tid >> 5] = s;
    __syncthreads();
    s = redsum[0];
#pragma unroll
    for (int i = 1; i < 8; i++) s += redsum[i];

    float inv = 1.0f / s;
    v.x *= inv; v.y *= inv; v.z *= inv; v.w *= inv;
    *(float4*)(p + tid * 4) = v;
}

extern "C" void kernel_launch(void* const* d_in, const int* in_sizes, int n_in,
                              void* d_out, int out_size) {
    const float* x0 = (const float*)d_in[0];   // [B,T,D]
    const float* x1 = (const float*)d_in[1];   // [B,T,D]
    const float* W  = (const float*)d_in[2];   // [D,D]
    float* out  = (float*)d_out;
    float* ws   = out;                                        // [B,T,T]
    float* attn = out + (size_t)BB * TT * TT;                 // [B,T,D]

    float* wt_ptr = nullptr;
    cudaGetSymbolAddress((void**)&wt_ptr, d_Wt);

    // 1) Wt = W^T  (so GEMM sees col-major B)
    transposeW<<<dim3(DD / 32, DD / 32), dim3(32, 8)>>>(W, wt_ptr);

    // 2) logits = x1 @ W  -> written into attention region of d_out
    //    M = B*T = 16384, N = D, K = D
    gemm_tf32<<<dim3(DD / BN, (BB * TT) / BM, 1), 256>>>(
        x1, wt_ptr, attn, DD, DD, DD, DD, 0, 0, 0);

    // 3) softmax in place over last axis
    softmax_rows<<<BB * TT, 256>>>(attn);

    // 4) weighted_sum[b] = attn[b] @ x0[b]^T   (batched NT GEMM)
    //    M = T, N = T, K = D
    gemm_tf32<<<dim3(TT / BN, TT / BM, BB), 256>>>(
        attn, x0, ws, DD, DD, DD, TT,
        (size_t)TT * DD, (size_t)TT * DD, (size_t)TT * TT);
}

// round 3
// speedup vs baseline: 1.0337x; 1.0337x over previous
#include <cuda_runtime.h>
#include <cuda_bf16.h>
#include <cstdint>
#include <cstddef>

// Problem constants
#define BB 8
#define TT 2048
#define DD 1024

// GEMM tiling
#define BM 128
#define BN 128
#define BK 32
#define SST 36   // smem row stride (floats): stride%32=4 -> conflict-free fragment loads

#define SMEM_FLOATS (2 * (BM + BN) * SST)
#define SMEM_BYTES  (SMEM_FLOATS * 4)

// Scratch: transposed W (col-major B operand for GEMM1). Device global = allowed.
__device__ float d_Wt[DD * DD];

__device__ __forceinline__ uint32_t f2tf32(float x) {
    uint32_t r;
    asm("cvt.rna.tf32.f32 %0, %1;" : "=r"(r) : "f"(x));
    return r;
}

__device__ __forceinline__ void cp_async16(uint32_t saddr, const float* g) {
    asm volatile("cp.async.cg.shared.global [%0], [%1], 16;" :: "r"(saddr), "l"(g));
}
__device__ __forceinline__ void cp_commit() {
    asm volatile("cp.async.commit_group;");
}
__device__ __forceinline__ void cp_wait_all() {
    asm volatile("cp.async.wait_group 0;");
}

__device__ __forceinline__ void mma_tf32(float c[4], const uint32_t a[4], const uint32_t b[2]) {
    asm volatile(
        "mma.sync.aligned.m16n8k8.row.col.f32.tf32.tf32.f32 "
        "{%0,%1,%2,%3}, {%4,%5,%6,%7}, {%8,%9}, {%0,%1,%2,%3};\n"
        : "+f"(c[0]), "+f"(c[1]), "+f"(c[2]), "+f"(c[3])
        : "r"(a[0]), "r"(a[1]), "r"(a[2]), "r"(a[3]), "r"(b[0]), "r"(b[1]));
}

// W [K][N] row-major -> Wt [N][K] row-major (i.e. col-major B)
__global__ void transposeW(const float* __restrict__ W, float* __restrict__ Wt) {
    __shared__ float tile[32][33];
    int bx = blockIdx.x * 32, by = blockIdx.y * 32;
    int tx = threadIdx.x, ty = threadIdx.y;
#pragma unroll
    for (int i = 0; i < 32; i += 8)
        tile[ty + i][tx] = W[(size_t)(by + ty + i) * DD + bx + tx];
    __syncthreads();
#pragma unroll
    for (int i = 0; i < 32; i += 8)
        Wt[(size_t)(bx + ty + i) * DD + by + tx] = tile[tx][ty + i];
}

// C[M,N] = A[M,K] (row-major, ld=lda) @ B[N,K]^T (B stored [n][k], ld=ldb)
// Double-buffered cp.async pipeline; fp32 in smem, tf32 cvt at fragment load.
__global__ __launch_bounds__(256) void gemm_tf32(
    const float* __restrict__ A, const float* __restrict__ Bm, float* __restrict__ C,
    int K, int lda, int ldb, int ldc,
    size_t aStride, size_t bStride, size_t cStride)
{
    extern __shared__ float smem[];
    float* sA = smem;                         // 2 * BM * SST
    float* sB = smem + 2 * BM * SST;          // 2 * BN * SST

    A  += (size_t)blockIdx.z * aStride;
    Bm += (size_t)blockIdx.z * bStride;
    C  += (size_t)blockIdx.z * cStride;

    const int tid  = threadIdx.x;
    const int warp = tid >> 5;
    const int lane = tid & 31;
    const int wm = warp & 3;      // 4 warps along M -> 32 rows each
    const int wn = warp >> 2;     // 2 warps along N -> 64 cols each
    const int g = lane >> 2;      // 0..7
    const int t = lane & 3;       // 0..3

    // global->smem load mapping: 256 threads, each 4x 16B per operand
    const int lrow = tid >> 3;        // 0..31 (+i*32)
    const int lk   = (tid & 7) * 4;   // 0..28

    const float* Ag = A  + (size_t)((size_t)blockIdx.y * BM + lrow) * lda + lk;
    const float* Bg = Bm + (size_t)((size_t)blockIdx.x * BN + lrow) * ldb + lk;

    const uint32_t sA_u = (uint32_t)__cvta_generic_to_shared(sA) + (uint32_t)(lrow * SST + lk) * 4u;
    const uint32_t sB_u = (uint32_t)__cvta_generic_to_shared(sB) + (uint32_t)(lrow * SST + lk) * 4u;

    float c[2][8][4];
#pragma unroll
    for (int mt = 0; mt < 2; mt++)
#pragma unroll
        for (int nt = 0; nt < 8; nt++)
#pragma unroll
            for (int i = 0; i < 4; i++) c[mt][nt][i] = 0.f;

    // prologue: stage k0 = 0 into buffer 0
#pragma unroll
    for (int i = 0; i < 4; i++) {
        cp_async16(sA_u + (uint32_t)(i * 32 * SST) * 4u, Ag + (size_t)i * 32 * lda);
        cp_async16(sB_u + (uint32_t)(i * 32 * SST) * 4u, Bg + (size_t)i * 32 * ldb);
    }
    cp_commit();
    cp_wait_all();
    __syncthreads();

    int buf = 0;
    for (int k0 = 0; k0 < K; k0 += BK) {
        // prefetch next tile into the other buffer (overlaps with compute below)
        if (k0 + BK < K) {
            const int nb = buf ^ 1;
            const float* Ap = Ag + (k0 + BK);
            const float* Bp = Bg + (k0 + BK);
            const uint32_t da = sA_u + (uint32_t)(nb * BM * SST) * 4u;
            const uint32_t db = sB_u + (uint32_t)(nb * BN * SST) * 4u;
#pragma unroll
            for (int i = 0; i < 4; i++) {
                cp_async16(da + (uint32_t)(i * 32 * SST) * 4u, Ap + (size_t)i * 32 * lda);
                cp_async16(db + (uint32_t)(i * 32 * SST) * 4u, Bp + (size_t)i * 32 * ldb);
            }
            cp_commit();
        }

        const float* cA = sA + buf * BM * SST;
        const float* cB = sB + buf * BN * SST;

#pragma unroll
        for (int ks = 0; ks < 4; ks++) {
            const int kk = ks * 8;
            uint32_t a[2][4], b[8][2];
#pragma unroll
            for (int mt = 0; mt < 2; mt++) {
                int rm = wm * 32 + mt * 16;
                a[mt][0] = f2tf32(cA[(rm + g)     * SST + kk + t]);
                a[mt][1] = f2tf32(cA[(rm + g + 8) * SST + kk + t]);
                a[mt][2] = f2tf32(cA[(rm + g)     * SST + kk + t + 4]);
                a[mt][3] = f2tf32(cA[(rm + g + 8) * SST + kk + t + 4]);
            }
#pragma unroll
            for (int nt = 0; nt < 8; nt++) {
                int rn = wn * 64 + nt * 8 + g;
                b[nt][0] = f2tf32(cB[rn * SST + kk + t]);
                b[nt][1] = f2tf32(cB[rn * SST + kk + t + 4]);
            }
#pragma unroll
            for (int mt = 0; mt < 2; mt++)
#pragma unroll
                for (int nt = 0; nt < 8; nt++)
                    mma_tf32(c[mt][nt], a[mt], b[nt]);
        }

        // wait for prefetch + make buffer swap safe
        cp_wait_all();
        __syncthreads();
        buf ^= 1;
    }

    // epilogue: c0/c1 contiguous along n -> float2 stores
    const int mbase = blockIdx.y * BM + wm * 32;
    const int nbase = blockIdx.x * BN + wn * 64;
#pragma unroll
    for (int mt = 0; mt < 2; mt++) {
        int row0 = mbase + mt * 16 + g;
#pragma unroll
        for (int nt = 0; nt < 8; nt++) {
            int col = nbase + nt * 8 + t * 2;
            float2 v0 = make_float2(c[mt][nt][0], c[mt][nt][1]);
            *(float2*)&C[(size_t)row0 * ldc + col] = v0;
            float2 v1 = make_float2(c[mt][nt][2], c[mt][nt][3]);
            *(float2*)&C[(size_t)(row0 + 8) * ldc + col] = v1;
        }
    }
}

// In-place softmax over rows of length 1024. One block (256 thr) per row.
__global__ __launch_bounds__(256) void softmax_rows(float* __restrict__ data) {
    __shared__ float redmax[8];
    __shared__ float redsum[8];
    float* p = data + (size_t)blockIdx.x * DD;
    const int tid = threadIdx.x;

    float4 v = *(float4*)(p + tid * 4);
    float m = fmaxf(fmaxf(v.x, v.y), fmaxf(v.z, v.w));
#pragma unroll
    for (int o = 16; o > 0; o >>= 1) m = fmaxf(m, __shfl_xor_sync(0xffffffffu, m, o));
    if ((tid & 31) == 0) redmax[tid >> 5] = m;
    __syncthreads();
    m = redmax[0];
#pragma unroll
    for (int i = 1; i < 8; i++) m = fmaxf(m, redmax[i]);

    v.x = __expf(v.x - m); v.y = __expf(v.y - m);
    v.z = __expf(v.z - m); v.w = __expf(v.w - m);
    float s = v.x + v.y + v.z + v.w;
#pragma unroll
    for (int o = 16; o > 0; o >>= 1) s += __shfl_xor_sync(0xffffffffu, s, o);
    if ((tid & 31) == 0) redsum[tid >> 5] = s;
    __syncthreads();
    s = redsum[0];
#pragma unroll
    for (int i = 1; i < 8; i++) s += redsum[i];

    float inv = 1.0f / s;
    v.x *= inv; v.y *= inv; v.z *= inv; v.w *= inv;
    *(float4*)(p + tid * 4) = v;
}

extern "C" void kernel_launch(void* const* d_in, const int* in_sizes, int n_in,
                              void* d_out, int out_size) {
    const float* x0 = (const float*)d_in[0];   // [B,T,D]
    const float* x1 = (const float*)d_in[1];   // [B,T,D]
    const float* W  = (const float*)d_in[2];   // [D,D]
    float* out  = (float*)d_out;
    float* ws   = out;                                        // [B,T,T]
    float* attn = out + (size_t)BB * TT * TT;                 // [B,T,D]

    float* wt_ptr = nullptr;
    cudaGetSymbolAddress((void**)&wt_ptr, d_Wt);

    static bool attr_done = false;
    if (!attr_done) {
        cudaFuncSetAttribute(gemm_tf32, cudaFuncAttributeMaxDynamicSharedMemorySize, SMEM_BYTES);
        attr_done = true;
    }

    // 1) Wt = W^T  (so GEMM sees col-major B)
    transposeW<<<dim3(DD / 32, DD / 32), dim3(32, 8)>>>(W, wt_ptr);

    // 2) logits = x1 @ W  -> written into attention region of d_out
    //    M = B*T = 16384, N = D, K = D
    gemm_tf32<<<dim3(DD / BN, (BB * TT) / BM, 1), 256, SMEM_BYTES>>>(
        x1, wt_ptr, attn, DD, DD, DD, DD, 0, 0, 0);

    // 3) softmax in place over last axis
    softmax_rows<<<BB * TT, 256>>>(attn);

    // 4) weighted_sum[b] = attn[b] @ x0[b]^T   (batched NT GEMM)
    //    M = T, N = T, K = D
    gemm_tf32<<<dim3(TT / BN, TT / BM, BB), 256, SMEM_BYTES>>>(
        attn, x0, ws, DD, DD, DD, TT,
        (size_t)TT * DD, (size_t)TT * DD, (size_t)TT * TT);
}

// round 6
// speedup vs baseline: 2.0208x; 1.9549x over previous
#include <cuda_runtime.h>
#include <cuda_fp16.h>
#include <cstdint>
#include <cstddef>

// Problem constants
#define BB 8
#define TT 2048
#define DD 1024

// GEMM tiling (fp16 operands, fp32 accum)
#define BM 128
#define BN 128
#define BK 64            // K halves per stage (128 B rows)
#define SROW 72          // smem row stride in halves: 72*2B=144B, bank pattern 4g+t conflict-free
#define TILE_HALVES (BM * SROW)                 // per operand per stage
#define SMEM_BYTES  (2 * 2 * TILE_HALVES * 2)   // 2 buffers * 2 operands * halves * 2B = 73728

// Scratch (device globals = allowed)
__device__ __half d_Wth[DD * DD];               // W^T as half [N][K]
__device__ __half d_x0h[BB * TT * DD];
__device__ __half d_x1h[BB * TT * DD];
__device__ __half d_attnh[BB * TT * DD];

__device__ __forceinline__ void cp_async16(uint32_t saddr, const void* g) {
    asm volatile("cp.async.cg.shared.global [%0], [%1], 16;" :: "r"(saddr), "l"(g));
}
__device__ __forceinline__ void cp_commit() { asm volatile("cp.async.commit_group;"); }
__device__ __forceinline__ void cp_wait0()  { asm volatile("cp.async.wait_group 0;"); }

__device__ __forceinline__ void mma_f16(float c[4], const uint32_t a[4], const uint32_t b[2]) {
    asm volatile(
        "mma.sync.aligned.m16n8k16.row.col.f32.f16.f16.f32 "
        "{%0,%1,%2,%3}, {%4,%5,%6,%7}, {%8,%9}, {%0,%1,%2,%3};\n"
        : "+f"(c[0]), "+f"(c[1]), "+f"(c[2]), "+f"(c[3])
        : "r"(a[0]), "r"(a[1]), "r"(a[2]), "r"(a[3]), "r"(b[0]), "r"(b[1]));
}

// ---------------------------------------------------------------- pre-passes
// fp32 -> fp16 streaming convert (4 floats / thread)
__global__ __launch_bounds__(256) void conv_f2h(const float* __restrict__ src,
                                                __half* __restrict__ dst, int n) {
    int i = (blockIdx.x * 256 + threadIdx.x) * 4;
    if (i >= n) return;
    float4 v = *(const float4*)(src + i);
    __half2 h0 = __floats2half2_rn(v.x, v.y);
    __half2 h1 = __floats2half2_rn(v.z, v.w);
    *(uint32_t*)(dst + i)     = *(uint32_t*)&h0;
    *(uint32_t*)(dst + i + 2) = *(uint32_t*)&h1;
}

// W [K][N] row-major -> Wt [N][K] half
__global__ void transposeW_h(const float* __restrict__ W, __half* __restrict__ Wt) {
    __shared__ float tile[32][33];
    int bx = blockIdx.x * 32, by = blockIdx.y * 32;
    int tx = threadIdx.x, ty = threadIdx.y;
#pragma unroll
    for (int i = 0; i < 32; i += 8)
        tile[ty + i][tx] = W[(size_t)(by + ty + i) * DD + bx + tx];
    __syncthreads();
#pragma unroll
    for (int i = 0; i < 32; i += 8)
        Wt[(size_t)(bx + ty + i) * DD + by + tx] = __float2half_rn(tile[tx][ty + i]);
}

// In-place fp32 softmax over rows of 1024, plus fp16 copy for GEMM2's A operand.
__global__ __launch_bounds__(256) void softmax_rows(float* __restrict__ data,
                                                    __half* __restrict__ data_h) {
    __shared__ float redmax[8];
    __shared__ float redsum[8];
    const size_t rowoff = (size_t)blockIdx.x * DD;
    float* p = data + rowoff;
    __half* ph = data_h + rowoff;
    const int tid = threadIdx.x;

    float4 v = *(float4*)(p + tid * 4);
    float m = fmaxf(fmaxf(v.x, v.y), fmaxf(v.z, v.w));
#pragma unroll
    for (int o = 16; o > 0; o >>= 1) m = fmaxf(m, __shfl_xor_sync(0xffffffffu, m, o));
    if ((tid & 31) == 0) redmax[tid >> 5] = m;
    __syncthreads();
    m = redmax[0];
#pragma unroll
    for (int i = 1; i < 8; i++) m = fmaxf(m, redmax[i]);

    v.x = __expf(v.x - m); v.y = __expf(v.y - m);
    v.z = __expf(v.z - m); v.w = __expf(v.w - m);
    float s = v.x + v.y + v.z + v.w;
#pragma unroll
    for (int o = 16; o > 0; o >>= 1) s += __shfl_xor_sync(0xffffffffu, s, o);
    if ((tid & 31) == 0) redsum[tid >> 5] = s;
    __syncthreads();
    s = redsum[0];
#pragma unroll
    for (int i = 1; i < 8; i++) s += redsum[i];

    float inv = 1.0f / s;
    v.x *= inv; v.y *= inv; v.z *= inv; v.w *= inv;
    *(float4*)(p + tid * 4) = v;
    __half2 h0 = __floats2half2_rn(v.x, v.y);
    __half2 h1 = __floats2half2_rn(v.z, v.w);
    *(uint32_t*)(ph + tid * 4)     = *(uint32_t*)&h0;
    *(uint32_t*)(ph + tid * 4 + 2) = *(uint32_t*)&h1;
}

// ---------------------------------------------------------------- fp16 tensor GEMM
// C[M,N] = A[M,K] (half, row-major) @ B[N,K]^T (half, [n][k]), C fp32.
// Double-buffered cp.async; warp tile 32x64; mma m16n8k16.
__global__ __launch_bounds__(256, 2) void gemm_f16(
    const __half* __restrict__ A, const __half* __restrict__ Bm, float* __restrict__ C,
    int K, int lda, int ldb, int ldc,
    size_t aStride, size_t bStride, size_t cStride)
{
    extern __shared__ __align__(16) __half smem[];
    __half* sA = smem;                      // 2 * TILE_HALVES
    __half* sB = smem + 2 * TILE_HALVES;    // 2 * TILE_HALVES

    A  += (size_t)blockIdx.z * aStride;
    Bm += (size_t)blockIdx.z * bStride;
    C  += (size_t)blockIdx.z * cStride;

    const int tid  = threadIdx.x;
    const int warp = tid >> 5;
    const int lane = tid & 31;
    const int wm = warp & 3;      // 4 warps along M -> 32 rows each
    const int wn = warp >> 2;     // 2 warps along N -> 64 cols each
    const int g = lane >> 2;      // 0..7
    const int t = lane & 3;       // 0..3

    // global->smem: 1024 16B-chunks per operand, 4 per thread.
    // chunk ch: row r = ch>>3 (0..127), col c = ch&7 (16B units; 8 halves)
    const int r0 = tid >> 3;          // rows r0 + i*32
    const int c0 = (tid & 7) * 8;     // halves

    const __half* Ag = A  + (size_t)((size_t)blockIdx.y * BM + r0) * lda + c0;
    const __half* Bg = Bm + (size_t)((size_t)blockIdx.x * BN + r0) * ldb + c0;

    const uint32_t sA_u = (uint32_t)__cvta_generic_to_shared(sA) + (uint32_t)(r0 * SROW + c0) * 2u;
    const uint32_t sB_u = (uint32_t)__cvta_generic_to_shared(sB) + (uint32_t)(r0 * SROW + c0) * 2u;

    float c[2][8][4];
#pragma unroll
    for (int mt = 0; mt < 2; mt++)
#pragma unroll
        for (int nt = 0; nt < 8; nt++)
#pragma unroll
            for (int i = 0; i < 4; i++) c[mt][nt][i] = 0.f;

    // prologue: stage 0 into buffer 0
#pragma unroll
    for (int i = 0; i < 4; i++) {
        cp_async16(sA_u + (uint32_t)(i * 32 * SROW) * 2u, Ag + (size_t)i * 32 * lda);
        cp_async16(sB_u + (uint32_t)(i * 32 * SROW) * 2u, Bg + (size_t)i * 32 * ldb);
    }
    cp_commit();
    cp_wait0();
    __syncthreads();

    int buf = 0;
    for (int k0 = 0; k0 < K; k0 += BK) {
        // prefetch next K-tile into other buffer (overlaps compute)
        if (k0 + BK < K) {
            const int nb = buf ^ 1;
            const __half* Ap = Ag + (k0 + BK);
            const __half* Bp = Bg + (k0 + BK);
            const uint32_t da = sA_u + (uint32_t)(nb * TILE_HALVES) * 2u;
            const uint32_t db = sB_u + (uint32_t)(nb * TILE_HALVES) * 2u;
#pragma unroll
            for (int i = 0; i < 4; i++) {
                cp_async16(da + (uint32_t)(i * 32 * SROW) * 2u, Ap + (size_t)i * 32 * lda);
                cp_async16(db + (uint32_t)(i * 32 * SROW) * 2u, Bp + (size_t)i * 32 * ldb);
            }
            cp_commit();
        }

        const __half* cA = sA + buf * TILE_HALVES;
        const __half* cB = sB + buf * TILE_HALVES;

#pragma unroll
        for (int ks = 0; ks < 4; ks++) {
            const int kk = ks * 16;           // k offset in halves
            uint32_t a[2][4], b[8][2];
#pragma unroll
            for (int mt = 0; mt < 2; mt++) {
                int rm = wm * 32 + mt * 16;
                const __half* pr0 = cA + (rm + g) * SROW + kk + 2 * t;
                const __half* pr1 = cA + (rm + g + 8) * SROW + kk + 2 * t;
                a[mt][0] = *(const uint32_t*)pr0;
                a[mt][1] = *(const uint32_t*)pr1;
                a[mt][2] = *(const uint32_t*)(pr0 + 8);
                a[mt][3] = *(const uint32_t*)(pr1 + 8);
            }
#pragma unroll
            for (int nt = 0; nt < 8; nt++) {
                int rn = wn * 64 + nt * 8 + g;
                const __half* pb = cB + rn * SROW + kk + 2 * t;
                b[nt][0] = *(const uint32_t*)pb;
                b[nt][1] = *(const uint32_t*)(pb + 8);
            }
#pragma unroll
            for (int mt = 0; mt < 2; mt++)
#pragma unroll
                for (int nt = 0; nt < 8; nt++)
                    mma_f16(c[mt][nt], a[mt], b[nt]);
        }

        cp_wait0();
        __syncthreads();
        buf ^= 1;
    }

    // epilogue: fp32 float2 stores (c0,c1 adjacent cols; c2,c3 row+8)
    const int mbase = blockIdx.y * BM + wm * 32;
    const int nbase = blockIdx.x * BN + wn * 64;
#pragma unroll
    for (int mt = 0; mt < 2; mt++) {
        int row0 = mbase + mt * 16 + g;
#pragma unroll
        for (int nt = 0; nt < 8; nt++) {
            int col = nbase + nt * 8 + t * 2;
            float2 v0 = make_float2(c[mt][nt][0], c[mt][nt][1]);
            *(float2*)&C[(size_t)row0 * ldc + col] = v0;
            float2 v1 = make_float2(c[mt][nt][2], c[mt][nt][3]);
            *(float2*)&C[(size_t)(row0 + 8) * ldc + col] = v1;
        }
    }
}

// ---------------------------------------------------------------- launch
extern "C" void kernel_launch(void* const* d_in, const int* in_sizes, int n_in,
                              void* d_out, int out_size) {
    const float* x0 = (const float*)d_in[0];   // [B,T,D]
    const float* x1 = (const float*)d_in[1];   // [B,T,D]
    const float* W  = (const float*)d_in[2];   // [D,D]
    float* out  = (float*)d_out;
    float* ws   = out;                                        // [B,T,T]
    float* attn = out + (size_t)BB * TT * TT;                 // [B,T,D]

    __half *wt_p, *x0h_p, *x1h_p, *attnh_p;
    cudaGetSymbolAddress((void**)&wt_p,   d_Wth);
    cudaGetSymbolAddress((void**)&x0h_p,  d_x0h);
    cudaGetSymbolAddress((void**)&x1h_p,  d_x1h);
    cudaGetSymbolAddress((void**)&attnh_p, d_attnh);

    static bool attr_done = false;
    if (!attr_done) {
        cudaFuncSetAttribute(gemm_f16, cudaFuncAttributeMaxDynamicSharedMemorySize, SMEM_BYTES);
        attr_done = true;
    }

    const int nElem = BB * TT * DD;

    // 0) convert inputs to fp16 once
    conv_f2h<<<nElem / 1024, 256>>>(x0, x0h_p, nElem);
    conv_f2h<<<nElem / 1024, 256>>>(x1, x1h_p, nElem);
    transposeW_h<<<dim3(DD / 32, DD / 32), dim3(32, 8)>>>(W, wt_p);

    // 1) logits = x1 @ W -> fp32 into attention region of d_out
    gemm_f16<<<dim3(DD / BN, (BB * TT) / BM, 1), 256, SMEM_BYTES>>>(
        x1h_p, wt_p, attn, DD, DD, DD, DD, 0, 0, 0);

    // 2) softmax in place (fp32) + fp16 copy
    softmax_rows<<<BB * TT, 256>>>(attn, attnh_p);

    // 3) weighted_sum[b] = attn[b] @ x0[b]^T
    gemm_f16<<<dim3(TT / BN, TT / BM, BB), 256, SMEM_BYTES>>>(
        attnh_p, x0h_p, ws, DD, DD, DD, TT,
        (size_t)TT * DD, (size_t)TT * DD, (size_t)TT * TT);
}